// round 1
// baseline (speedup 1.0000x reference)
#include <cuda_runtime.h>
#include <cstdint>

// GraphConv: out[row[e], :] += edge_vals[e] * x[col[e], :]   (D_FEAT = 64)
// Strategy: one 16-lane half-warp per edge; float4 gather from x, scaled,
// scattered with red.global.add.v4.f32 (vector reduction, no return value).

#define D_FEAT 64
#define D_VEC4 16  // 64 floats = 16 float4

__global__ void __launch_bounds__(256) graphconv_kernel(
    const float4* __restrict__ x4,       // [N_NODES * 16] float4
    const float*  __restrict__ edge_vals,
    const int*    __restrict__ row,
    const int*    __restrict__ col,
    float*        __restrict__ out,      // [N_NODES * 64] floats
    int n_edges)
{
    const int lane16 = threadIdx.x & 15;
    const long long gtid = (long long)blockIdx.x * blockDim.x + threadIdx.x;
    const long long hw   = gtid >> 4;                       // half-warp id
    const long long n_hw = ((long long)gridDim.x * blockDim.x) >> 4;

    for (long long e = hw; e < n_edges; e += n_hw) {
        const int   r = __ldg(row + e);
        const int   c = __ldg(col + e);
        const float v = __ldg(edge_vals + e);

        float4 xv = __ldg(x4 + (long long)c * D_VEC4 + lane16);

        float4 m;
        m.x = xv.x * v;
        m.y = xv.y * v;
        m.z = xv.z * v;
        m.w = xv.w * v;

        float* dst = out + (long long)r * D_FEAT + lane16 * 4;
        asm volatile(
            "red.global.add.v4.f32 [%0], {%1, %2, %3, %4};"
            :: "l"(dst), "f"(m.x), "f"(m.y), "f"(m.z), "f"(m.w)
            : "memory");
    }
}

extern "C" void kernel_launch(void* const* d_in, const int* in_sizes, int n_in,
                              void* d_out, int out_size)
{
    const float* x         = (const float*)d_in[0];
    const float* edge_vals = (const float*)d_in[1];
    const int*   row       = (const int*)d_in[2];
    const int*   col       = (const int*)d_in[3];
    float*       out       = (float*)d_out;

    const int n_edges = in_sizes[1];

    // Output is poisoned; zero it first (memset node is graph-capturable).
    cudaMemsetAsync(out, 0, (size_t)out_size * sizeof(float));

    // Fill the chip: 148 SMs x 2048 threads = 1184 blocks of 256.
    const int threads = 256;
    const int blocks  = 1184;
    graphconv_kernel<<<blocks, threads>>>(
        (const float4*)x, edge_vals, row, col, out, n_edges);
}